// round 11
// baseline (speedup 1.0000x reference)
#include <cuda_runtime.h>
#include <cstdint>
#include <math.h>

#define B_ 4
#define T_ 2048
#define C_ 1024
#define H_ 16
#define D_ 64

static const long long Y_ELEMS   = (long long)B_ * T_ * C_;        // 8,388,608
static const long long ATT_ELEMS = (long long)B_ * H_ * T_ * T_;   // 268,435,456

// Scratch (device globals: allocation-free per harness rules)
__device__ float g_q[(size_t)B_ * H_ * T_ * D_];
__device__ float g_k[(size_t)B_ * H_ * T_ * D_];
__device__ float g_v[(size_t)B_ * H_ * T_ * D_];
__device__ float g_yh[(size_t)B_ * T_ * C_];
__device__ float g_att_fb[(size_t)B_ * H_ * T_ * T_];
__device__ float g_xr[(size_t)B_ * T_ * C_];
__device__ float g_wqr[(size_t)C_ * C_];
__device__ float g_wkr[(size_t)C_ * C_];
__device__ float g_wvr[(size_t)C_ * C_];
__device__ float g_wpr[(size_t)C_ * C_];

// ---------------------------------------------------------------------------
// PTX helpers
// ---------------------------------------------------------------------------
__device__ __forceinline__ unsigned cvt_tf32(float x) {
    unsigned r;
    asm("cvt.rna.tf32.f32 %0, %1;" : "=r"(r) : "f"(x));
    return r;
}
__device__ __forceinline__ float rnd_tf32(float x) {
    return __uint_as_float(cvt_tf32(x));
}

__device__ __forceinline__ void mma_tf32(float c[4],
                                         unsigned a0, unsigned a1, unsigned a2, unsigned a3,
                                         unsigned b0, unsigned b1) {
    asm volatile(
        "mma.sync.aligned.m16n8k8.row.col.f32.tf32.tf32.f32 "
        "{%0,%1,%2,%3},{%4,%5,%6,%7},{%8,%9},{%0,%1,%2,%3};\n"
        : "+f"(c[0]), "+f"(c[1]), "+f"(c[2]), "+f"(c[3])
        : "r"(a0), "r"(a1), "r"(a2), "r"(a3), "r"(b0), "r"(b1));
}

__device__ __forceinline__ void cp_async16(float* smem, const float* gmem) {
    uint32_t s = (uint32_t)__cvta_generic_to_shared(smem);
    asm volatile("cp.async.cg.shared.global [%0], [%1], 16;\n" :: "r"(s), "l"(gmem));
}
__device__ __forceinline__ void cp_commit() {
    asm volatile("cp.async.commit_group;\n");
}
template <int N>
__device__ __forceinline__ void cp_wait() {
    asm volatile("cp.async.wait_group %0;\n" :: "n"(N));
}

// k-permutation within every 8-block: natural k=(ks,h,tig) -> pos = 2*tig + h.
// Fragment slots (k=tig, k=tig+4) land at adjacent pos (2tig, 2tig+1) -> LDS.64.
__device__ __host__ __forceinline__ int perm8(int k) {
    return ((k & 3) << 1) | ((k >> 2) & 1);
}

#define LDT 40   // dense tiles: 40 % 32 == 8 -> uint2 frag loads conflict-free
#define LQK 72   // flash Q/K tiles (72 % 32 == 8), also V ([k][n], 8tig+g pattern)
#define LP  68   // flash P tile, natural scalar loads (68 % 32 == 4 -> 4g+tig free)

// ---------------------------------------------------------------------------
// Pre-round to tf32-rna AND apply perm8 to the contiguous (k) dim.
// Processes 8 floats per thread; rows are multiples of 8 so blocks never span rows.
// ---------------------------------------------------------------------------
__global__ void round_perm_k(const float* __restrict__ in, float* __restrict__ out, int n8)
{
    int i = blockIdx.x * 256 + threadIdx.x;
    if (i < n8) {
        const float4 a = ((const float4*)in)[i * 2];
        const float4 b = ((const float4*)in)[i * 2 + 1];
        float2* o = (float2*)(out + (size_t)i * 8);
        o[0] = make_float2(rnd_tf32(a.x), rnd_tf32(b.x));
        o[1] = make_float2(rnd_tf32(a.y), rnd_tf32(b.y));
        o[2] = make_float2(rnd_tf32(a.z), rnd_tf32(b.z));
        o[3] = make_float2(rnd_tf32(a.w), rnd_tf32(b.w));
    }
}

// ---------------------------------------------------------------------------
// Dense GEMM core: C = A @ B^T (+ bias). A,B k-dims pre-permuted + rounded.
// CTA 256x128, BK=32, 3-stage cp.async. 8 warps (4m x 2n), warp tile 64x64.
// Frag loads are LDS.64. Per k-step: 16 LDS.64 feed 32 mma.
// cmode: 0 = dense row-major out; 1 = scatter (B,H,T,D) natural d;
//        2 = scatter (B,H,T,D) with perm8 on d (for q,k feeding flash).
// ---------------------------------------------------------------------------
__device__ __forceinline__
void gemm_core(const float* __restrict__ A, const float* __restrict__ Bm,
               const float* __restrict__ bias, float* __restrict__ Cc,
               int N, int K, int cmode, int round_out, float* sh)
{
    const int KC = K >> 5;
    float* As = sh;                    // [3][256][LDT]
    float* Bs = sh + 3 * 256 * LDT;    // [3][128][LDT]

    const int tid  = threadIdx.x;
    const int warp = tid >> 5;
    const int lane = tid & 31;
    const int g    = lane >> 2;
    const int tig  = lane & 3;
    const int wm   = warp >> 1;        // 0..3  (64-row slice)
    const int wn   = warp & 1;         // 0..1  (64-col slice)

    const int m0 = blockIdx.y * 256;
    const int n0 = blockIdx.x * 128;
    const int brow = tid >> 1;
    const int bo   = (tid & 1) * 16;

    float acc[4][8][4];
#pragma unroll
    for (int mi = 0; mi < 4; mi++)
#pragma unroll
        for (int ni = 0; ni < 8; ni++)
#pragma unroll
            for (int q = 0; q < 4; q++) acc[mi][ni][q] = 0.f;

    auto load_chunk = [&](int st, int kc) {
        const float* Ag = A + (long long)(m0 + tid) * K + kc * 32;
        float* as = As + st * 256 * LDT + tid * LDT;
#pragma unroll
        for (int i = 0; i < 8; i++) cp_async16(as + i * 4, Ag + i * 4);
        const float* Bg = Bm + (long long)(n0 + brow) * K + kc * 32 + bo;
        float* bs = Bs + st * 128 * LDT + brow * LDT + bo;
#pragma unroll
        for (int i = 0; i < 4; i++) cp_async16(bs + i * 4, Bg + i * 4);
        cp_commit();
    };

    auto compute = [&](int st) {
        const uint2* au = (const uint2*)(As + st * 256 * LDT) + (wm * 64) * (LDT / 2);
        const uint2* bu = (const uint2*)(Bs + st * 128 * LDT) + (wn * 64) * (LDT / 2);
#pragma unroll
        for (int ks = 0; ks < 4; ks++) {
            const int kb = ks * 4 + tig;
            uint2 alo[4], ahi[4], bb[8];
#pragma unroll
            for (int mi = 0; mi < 4; mi++) {
                alo[mi] = au[(mi * 16 + g) * (LDT / 2) + kb];
                ahi[mi] = au[(mi * 16 + g + 8) * (LDT / 2) + kb];
            }
#pragma unroll
            for (int ni = 0; ni < 8; ni++)
                bb[ni] = bu[(ni * 8 + g) * (LDT / 2) + kb];
#pragma unroll
            for (int mi = 0; mi < 4; mi++)
#pragma unroll
                for (int ni = 0; ni < 8; ni++)
                    mma_tf32(acc[mi][ni], alo[mi].x, ahi[mi].x, alo[mi].y, ahi[mi].y,
                             bb[ni].x, bb[ni].y);
        }
    };

    load_chunk(0, 0);
    if (KC > 1) load_chunk(1, 1);
    for (int kc = 0; kc < KC; kc++) {
        cp_wait<1>();
        __syncthreads();
        if (kc + 2 < KC) load_chunk((kc + 2) % 3, kc + 2);
        compute(kc % 3);
    }

#pragma unroll
    for (int mi = 0; mi < 4; mi++) {
        const int r0 = m0 + wm * 64 + mi * 16 + g;
        const int r1 = r0 + 8;
#pragma unroll
        for (int ni = 0; ni < 8; ni++) {
            const int c = n0 + wn * 64 + ni * 8 + tig * 2;
            const float b0v = bias ? bias[c]     : 0.f;
            const float b1v = bias ? bias[c + 1] : 0.f;
            float v00 = acc[mi][ni][0] + b0v;
            float v01 = acc[mi][ni][1] + b1v;
            float v10 = acc[mi][ni][2] + b0v;
            float v11 = acc[mi][ni][3] + b1v;
            if (round_out) {
                v00 = rnd_tf32(v00); v01 = rnd_tf32(v01);
                v10 = rnd_tf32(v10); v11 = rnd_tf32(v11);
            }
            if (cmode == 0) {
                *(float2*)&Cc[(long long)r0 * N + c] = make_float2(v00, v01);
                *(float2*)&Cc[(long long)r1 * N + c] = make_float2(v10, v11);
            } else {
                const int h = c >> 6;
                const int dd = c & 63;
                int d0 = dd, d1 = dd + 1;
                if (cmode == 2) {
                    d0 = (dd & ~7) | perm8(dd & 7);
                    d1 = (dd & ~7) | perm8((dd & 7) + 1);
                }
                const int b0i = r0 >> 11, t0 = r0 & 2047;
                const int b1i = r1 >> 11, t1 = r1 & 2047;
                float* p0 = &Cc[((long long)(b0i * H_ + h) * T_ + t0) * D_];
                float* p1 = &Cc[((long long)(b1i * H_ + h) * T_ + t1) * D_];
                if (cmode == 2) {
                    p0[d0] = v00; p0[d1] = v01;
                    p1[d0] = v10; p1[d1] = v11;
                } else {
                    *(float2*)&p0[d0] = make_float2(v00, v01);
                    *(float2*)&p1[d0] = make_float2(v10, v11);
                }
            }
        }
    }
}

// Merged Q/K/V projections: blockIdx.z selects weight/bias/output.
__global__ __launch_bounds__(256)
void qkv_gemm(const float* __restrict__ xr,
              const float* __restrict__ wq, const float* __restrict__ wk,
              const float* __restrict__ wv,
              const float* __restrict__ bq, const float* __restrict__ bk,
              const float* __restrict__ bv,
              float* __restrict__ q, float* __restrict__ k, float* __restrict__ v)
{
    extern __shared__ float sh[];
    if (blockIdx.z == 0)      gemm_core(xr, wq, bq, q, C_, C_, 2, 1, sh);
    else if (blockIdx.z == 1) gemm_core(xr, wk, bk, k, C_, C_, 2, 1, sh);
    else                      gemm_core(xr, wv, bv, v, C_, C_, 1, 1, sh);
}

__global__ __launch_bounds__(256)
void proj_gemm(const float* __restrict__ A, const float* __restrict__ Bm,
               const float* __restrict__ bias, float* __restrict__ Cc)
{
    extern __shared__ float sh[];
    gemm_core(A, Bm, bias, Cc, C_, C_, 0, 0, sh);
}

// ---------------------------------------------------------------------------
// Two-pass flash attention. Per CTA: 256 query rows x one head. 8 warps,
// each owns 32 rows x all 64 key-cols. Q/K d-dim is perm8'd in gmem ->
// QK^T frag loads are LDS.64. P/V stay natural (scalar loads, conflict-free).
// smem: Qs[256][LQK], Ks[2][64][LQK], Vs[2][64][LQK], Ps[256][LP], Ms[2][64]
//       = 217,600 B
// ---------------------------------------------------------------------------
__global__ __launch_bounds__(256)
void flash_att(const float* __restrict__ q, const float* __restrict__ k,
               const float* __restrict__ v, const float* __restrict__ mask,
               float* __restrict__ att, float* __restrict__ Y)
{
    const int z = blockIdx.z;
    const int b = z >> 4, h = z & 15;
    const int m0 = blockIdx.y * 256;
    const float* Qg = q + (long long)z * T_ * D_;
    const float* Kg = k + (long long)z * T_ * D_;
    const float* Vg = v + (long long)z * T_ * D_;
    float* Sg = att + (long long)z * T_ * T_;
    const float* mrow = mask + (long long)b * T_;

    extern __shared__ float sh[];
    float* Qs = sh;                          // 256*LQK
    float* Ks = Qs + 256 * LQK;              // 2*64*LQK
    float* Vs = Ks + 2 * 64 * LQK;           // 2*64*LQK
    float* Ps = Vs + 2 * 64 * LQK;           // 256*LP
    float* Ms = Ps + 256 * LP;               // 2*64

    const int tid  = threadIdx.x;
    const int warp = tid >> 5;               // 0..7: 32-row slice
    const int lane = tid & 31;
    const int g    = lane >> 2;
    const int tig  = lane & 3;

    // Q load (once): 256 rows x 64 (gmem already perm8'd in d)
    {
        const float* src = Qg + (long long)(m0 + tid) * D_;
        float* dst = Qs + tid * LQK;
#pragma unroll
        for (int i = 0; i < 16; i++) cp_async16(dst + i * 4, src + i * 4);
        cp_commit();
    }

    const int krow = tid >> 2;               // 0..63
    const int kc4  = (tid & 3) * 16;

    auto load_k = [&](int st, int kc) {
        const float* src = Kg + (long long)(kc * 64 + krow) * D_ + kc4;
        float* dst = Ks + st * 64 * LQK + krow * LQK + kc4;
#pragma unroll
        for (int i = 0; i < 4; i++) cp_async16(dst + i * 4, src + i * 4);
    };
    auto load_v = [&](int st, int kc) {
        const float* src = Vg + (long long)(kc * 64 + krow) * D_ + kc4;
        float* dst = Vs + st * 64 * LQK + krow * LQK + kc4;
#pragma unroll
        for (int i = 0; i < 4; i++) cp_async16(dst + i * 4, src + i * 4);
    };
    auto load_m = [&](int st, int kc) {
        if (tid < 16) cp_async16(Ms + st * 64 + tid * 4, mrow + kc * 64 + tid * 4);
    };

    // s-mma: warp computes 32 rows x 64 cols vs Ks[st]; LDS.64 frag loads
    float sacc[2][8][4];
    auto smma = [&](int st) {
#pragma unroll
        for (int mi = 0; mi < 2; mi++)
#pragma unroll
            for (int ni = 0; ni < 8; ni++)
#pragma unroll
                for (int qq = 0; qq < 4; qq++) sacc[mi][ni][qq] = 0.f;
        const uint2* au = (const uint2*)Qs + (warp * 32) * (LQK / 2);
        const uint2* bu = (const uint2*)(Ks + st * 64 * LQK);
#pragma unroll
        for (int ks = 0; ks < 8; ks++) {
            const int kb = ks * 4 + tig;
            uint2 alo[2], ahi[2], bb[8];
#pragma unroll
            for (int mi = 0; mi < 2; mi++) {
                alo[mi] = au[(mi * 16 + g) * (LQK / 2) + kb];
                ahi[mi] = au[(mi * 16 + g + 8) * (LQK / 2) + kb];
            }
#pragma unroll
            for (int ni = 0; ni < 8; ni++)
                bb[ni] = bu[(ni * 8 + g) * (LQK / 2) + kb];
#pragma unroll
            for (int mi = 0; mi < 2; mi++)
#pragma unroll
                for (int ni = 0; ni < 8; ni++)
                    mma_tf32(sacc[mi][ni], alo[mi].x, ahi[mi].x, alo[mi].y, ahi[mi].y,
                             bb[ni].x, bb[ni].y);
        }
    };

    const int NC = T_ / 64;   // 32 chunks

    // ------------------ Pass A: exp-sum (registers only) ------------------
    float rsum[2][2] = {{0.f, 0.f}, {0.f, 0.f}};
    load_k(0, 0); cp_commit();
    for (int kc = 0; kc < NC; kc++) {
        cp_wait<0>();
        __syncthreads();
        if (kc + 1 < NC) { load_k((kc + 1) & 1, kc + 1); cp_commit(); }
        smma(kc & 1);
#pragma unroll
        for (int mi = 0; mi < 2; mi++)
#pragma unroll
            for (int ni = 0; ni < 8; ni++) {
                rsum[mi][0] += __expf(sacc[mi][ni][0] * 0.125f)
                             + __expf(sacc[mi][ni][1] * 0.125f);
                rsum[mi][1] += __expf(sacc[mi][ni][2] * 0.125f)
                             + __expf(sacc[mi][ni][3] * 0.125f);
            }
    }
    float il[2][2];
#pragma unroll
    for (int mi = 0; mi < 2; mi++)
#pragma unroll
        for (int s2 = 0; s2 < 2; s2++) {
            float vv = rsum[mi][s2];
            vv += __shfl_xor_sync(0xffffffffu, vv, 1);
            vv += __shfl_xor_sync(0xffffffffu, vv, 2);
            il[mi][s2] = 1.f / vv;
        }

    // ------------------ Pass B: att write + P@V ------------------
    float yacc[2][8][4];
#pragma unroll
    for (int mi = 0; mi < 2; mi++)
#pragma unroll
        for (int ni = 0; ni < 8; ni++) {
            yacc[mi][ni][0] = 0.f; yacc[mi][ni][1] = 0.f;
            yacc[mi][ni][2] = 0.f; yacc[mi][ni][3] = 0.f;
        }

    load_k(0, 0); load_v(0, 0); load_m(0, 0); cp_commit();
    for (int kc = 0; kc < NC; kc++) {
        cp_wait<0>();
        __syncthreads();
        if (kc + 1 < NC) {
            const int st = (kc + 1) & 1;
            load_k(st, kc + 1); load_v(st, kc + 1); load_m(st, kc + 1);
            cp_commit();
        }
        const int st = kc & 1;
        smma(st);

        // epilogue: p = exp(s)*invl*mask -> att (global, st.cs) + Ps (smem, rounded)
#pragma unroll
        for (int mi = 0; mi < 2; mi++) {
            const int r0l = warp * 32 + mi * 16 + g;
            const int r1l = r0l + 8;
            const float il0 = il[mi][0];
            const float il1 = il[mi][1];
#pragma unroll
            for (int ni = 0; ni < 8; ni++) {
                const int cl = ni * 8 + tig * 2;
                const float mk0 = Ms[st * 64 + cl];
                const float mk1 = Ms[st * 64 + cl + 1];
                const float p00 = __expf(sacc[mi][ni][0] * 0.125f) * il0 * mk0;
                const float p01 = __expf(sacc[mi][ni][1] * 0.125f) * il0 * mk1;
                const float p10 = __expf(sacc[mi][ni][2] * 0.125f) * il1 * mk0;
                const float p11 = __expf(sacc[mi][ni][3] * 0.125f) * il1 * mk1;
                const long long gc = (long long)kc * 64 + cl;
                __stcs((float2*)&Sg[(long long)(m0 + r0l) * T_ + gc], make_float2(p00, p01));
                __stcs((float2*)&Sg[(long long)(m0 + r1l) * T_ + gc], make_float2(p10, p11));
                Ps[r0l * LP + cl]     = rnd_tf32(p00);
                Ps[r0l * LP + cl + 1] = rnd_tf32(p01);
                Ps[r1l * LP + cl]     = rnd_tf32(p10);
                Ps[r1l * LP + cl + 1] = rnd_tf32(p11);
            }
        }
        __syncthreads();

        // P@V: warp 32 rows x 64 D-cols, k = 64 keys (natural order both sides)
        {
            const unsigned* au = (const unsigned*)Ps + (warp * 32) * LP;
            const unsigned* bu = (const unsigned*)(Vs + st * 64 * LQK);
#pragma unroll
            for (int ks = 0; ks < 8; ks++) {
                const int kk = ks * 8;
                unsigned af[2][4], bf[8][2];
#pragma unroll
                for (int mi = 0; mi < 2; mi++) {
                    const int base = (mi * 16 + g) * LP + kk + tig;
                    af[mi][0] = au[base];
                    af[mi][1] = au[base + 8 * LP];
                    af[mi][2] = au[base + 4];
                    af[mi][3] = au[base + 8 * LP + 4];
                }
#pragma unroll
                for (int ni = 0; ni < 8; ni++) {
                    const int ncol = ni * 8 + g;
                    bf[ni][0] = bu[(kk + tig) * LQK + ncol];
                    bf[ni][1] = bu[(kk + tig + 4) * LQK + ncol];
                }
#pragma unroll
                for (int mi = 0; mi < 2; mi++)
#pragma unroll
                    for (int ni = 0; ni < 8; ni++)
                        mma_tf32(yacc[mi][ni], af[mi][0], af[mi][1], af[mi][2], af[mi][3],
                                 bf[ni][0], bf[ni][1]);
            }
        }
    }

    // write Y to (B,T,C) with perm8 on d (feeds the permuted-k proj GEMM)
#pragma unroll
    for (int mi = 0; mi < 2; mi++) {
        const int t0 = m0 + warp * 32 + mi * 16 + g;
        const int t1 = t0 + 8;
#pragma unroll
        for (int ni = 0; ni < 8; ni++) {
            const int dd = ni * 8 + tig * 2;
            const int d0 = (dd & ~7) | perm8(dd & 7);
            const int d1 = (dd & ~7) | perm8((dd & 7) + 1);
            float* p0 = &Y[(long long)(b * T_ + t0) * C_ + h * D_];
            float* p1 = &Y[(long long)(b * T_ + t1) * C_ + h * D_];
            p0[d0] = rnd_tf32(yacc[mi][ni][0]);
            p0[d1] = rnd_tf32(yacc[mi][ni][1]);
            p1[d0] = rnd_tf32(yacc[mi][ni][2]);
            p1[d1] = rnd_tf32(yacc[mi][ni][3]);
        }
    }
}

// ---------------------------------------------------------------------------
// Launch
// ---------------------------------------------------------------------------
extern "C" void kernel_launch(void* const* d_in, const int* in_sizes, int n_in,
                              void* d_out, int out_size)
{
    const float* x    = (const float*)d_in[0];
    const float* mask = (const float*)d_in[2];
    const float* Wq   = (const float*)d_in[3];
    const float* bq   = (const float*)d_in[4];
    const float* Wk   = (const float*)d_in[5];
    const float* bk   = (const float*)d_in[6];
    const float* Wv   = (const float*)d_in[7];
    const float* bv   = (const float*)d_in[8];
    const float* Wp   = (const float*)d_in[9];
    const float* bp   = (const float*)d_in[10];
    float* out = (float*)d_out;

    float *pq, *pk, *pv, *py, *patt_fb, *pxr, *pwq, *pwk, *pwv, *pwp;
    cudaGetSymbolAddress((void**)&pq, g_q);
    cudaGetSymbolAddress((void**)&pk, g_k);
    cudaGetSymbolAddress((void**)&pv, g_v);
    cudaGetSymbolAddress((void**)&py, g_yh);
    cudaGetSymbolAddress((void**)&patt_fb, g_att_fb);
    cudaGetSymbolAddress((void**)&pxr, g_xr);
    cudaGetSymbolAddress((void**)&pwq, g_wqr);
    cudaGetSymbolAddress((void**)&pwk, g_wkr);
    cudaGetSymbolAddress((void**)&pwv, g_wvr);
    cudaGetSymbolAddress((void**)&pwp, g_wpr);

    float* yout;
    float* att;
    if ((long long)out_size >= Y_ELEMS + ATT_ELEMS) {
        yout = out;  att = out + Y_ELEMS;
    } else if ((long long)out_size == ATT_ELEMS) {
        yout = nullptr;  att = out;
    } else {
        yout = out;  att = patt_fb;
    }

    const int GEMM_SMEM  = 3 * (256 + 128) * LDT * 4;               // 184,320 B
    const int FLASH_SMEM = (256 * LQK + 2 * 64 * LQK + 2 * 64 * LQK
                            + 256 * LP + 128) * 4;                  // 217,600 B
    cudaFuncSetAttribute(qkv_gemm,  cudaFuncAttributeMaxDynamicSharedMemorySize, GEMM_SMEM);
    cudaFuncSetAttribute(proj_gemm, cudaFuncAttributeMaxDynamicSharedMemorySize, GEMM_SMEM);
    cudaFuncSetAttribute(flash_att, cudaFuncAttributeMaxDynamicSharedMemorySize, FLASH_SMEM);

    const dim3 blk(256);

    // 0) pre-round + perm8 the k-dims of x and all weights
    round_perm_k<<<(int)(Y_ELEMS / 8 + 255) / 256, 256>>>(x, pxr, (int)(Y_ELEMS / 8));
    round_perm_k<<<(C_ * C_ / 8 + 255) / 256, 256>>>(Wq, pwq, C_ * C_ / 8);
    round_perm_k<<<(C_ * C_ / 8 + 255) / 256, 256>>>(Wk, pwk, C_ * C_ / 8);
    round_perm_k<<<(C_ * C_ / 8 + 255) / 256, 256>>>(Wv, pwv, C_ * C_ / 8);
    round_perm_k<<<(C_ * C_ / 8 + 255) / 256, 256>>>(Wp, pwp, C_ * C_ / 8);

    // 1) merged Q/K/V projections -> rounded, scattered to (B,H,T,D)
    //    (q,k with perm8'd d for the flash kernel; v natural)
    qkv_gemm<<<dim3(C_ / 128, (B_ * T_) / 256, 3), blk, GEMM_SMEM>>>(
        pxr, pwq, pwk, pwv, bq, bk, bv, pq, pk, pv);

    // 2) fused two-pass flash attention: att (written once) + Y heads
    flash_att<<<dim3(1, T_ / 256, B_ * H_), blk, FLASH_SMEM>>>(
        pq, pk, pv, mask, att, py);

    // 3) output projection (py and Wp both k-permuted; output natural)
    if (yout)
        proj_gemm<<<dim3(C_ / 128, (B_ * T_) / 256, 1), blk, GEMM_SMEM>>>(py, pwp, bp, yout);
}

// round 12
// speedup vs baseline: 1.0696x; 1.0696x over previous
#include <cuda_runtime.h>
#include <cstdint>
#include <math.h>

#define B_ 4
#define T_ 2048
#define C_ 1024
#define H_ 16
#define D_ 64

static const long long Y_ELEMS   = (long long)B_ * T_ * C_;        // 8,388,608
static const long long ATT_ELEMS = (long long)B_ * H_ * T_ * T_;   // 268,435,456

// Scratch (device globals: allocation-free per harness rules)
__device__ float g_q[(size_t)B_ * H_ * T_ * D_];
__device__ float g_k[(size_t)B_ * H_ * T_ * D_];
__device__ float g_v[(size_t)B_ * H_ * T_ * D_];
__device__ float g_yh[(size_t)B_ * T_ * C_];
__device__ float g_att_fb[(size_t)B_ * H_ * T_ * T_];
__device__ float g_xr[(size_t)B_ * T_ * C_];
__device__ float g_wqr[(size_t)C_ * C_];
__device__ float g_wkr[(size_t)C_ * C_];
__device__ float g_wvr[(size_t)C_ * C_];
__device__ float g_wpr[(size_t)C_ * C_];

// ---------------------------------------------------------------------------
// PTX helpers
// ---------------------------------------------------------------------------
__device__ __forceinline__ unsigned cvt_tf32(float x) {
    unsigned r;
    asm("cvt.rna.tf32.f32 %0, %1;" : "=r"(r) : "f"(x));
    return r;
}
__device__ __forceinline__ float rnd_tf32(float x) {
    return __uint_as_float(cvt_tf32(x));
}

__device__ __forceinline__ void mma_tf32(float c[4],
                                         unsigned a0, unsigned a1, unsigned a2, unsigned a3,
                                         unsigned b0, unsigned b1) {
    asm volatile(
        "mma.sync.aligned.m16n8k8.row.col.f32.tf32.tf32.f32 "
        "{%0,%1,%2,%3},{%4,%5,%6,%7},{%8,%9},{%0,%1,%2,%3};\n"
        : "+f"(c[0]), "+f"(c[1]), "+f"(c[2]), "+f"(c[3])
        : "r"(a0), "r"(a1), "r"(a2), "r"(a3), "r"(b0), "r"(b1));
}

__device__ __forceinline__ void cp_async16(float* smem, const float* gmem) {
    uint32_t s = (uint32_t)__cvta_generic_to_shared(smem);
    asm volatile("cp.async.cg.shared.global [%0], [%1], 16;\n" :: "r"(s), "l"(gmem));
}
__device__ __forceinline__ void cp_commit() {
    asm volatile("cp.async.commit_group;\n");
}
template <int N>
__device__ __forceinline__ void cp_wait() {
    asm volatile("cp.async.wait_group %0;\n" :: "n"(N));
}

// k-permutation within every 8-block: natural k -> pos = 2*(k&3) + (k>>2).
// Fragment slots (k=tig, k=tig+4) land at adjacent pos (2tig, 2tig+1) -> LDS.64.
__device__ __host__ __forceinline__ int perm8(int k) {
    return ((k & 3) << 1) | ((k >> 2) & 1);
}
// sigma = perm8^{-1}: C-fragment column c -> mma contraction slot sigma(c).
__device__ __forceinline__ int sigma8(int j) {
    return (j >> 1) | ((j & 1) << 2);
}

#define LDT 40   // dense tiles: uint2 frag loads conflict-free per 16-lane phase
#define LQK 72   // flash Q/K tiles (uint2 loads) and V ([k][n] scalar, 8tig+g free)

// ---------------------------------------------------------------------------
// Pre-round to tf32-rna AND apply perm8 to the contiguous (k) dim.
// ---------------------------------------------------------------------------
__global__ void round_perm_k(const float* __restrict__ in, float* __restrict__ out, int n8)
{
    int i = blockIdx.x * 256 + threadIdx.x;
    if (i < n8) {
        const float4 a = ((const float4*)in)[i * 2];
        const float4 b = ((const float4*)in)[i * 2 + 1];
        float2* o = (float2*)(out + (size_t)i * 8);
        o[0] = make_float2(rnd_tf32(a.x), rnd_tf32(b.x));
        o[1] = make_float2(rnd_tf32(a.y), rnd_tf32(b.y));
        o[2] = make_float2(rnd_tf32(a.z), rnd_tf32(b.z));
        o[3] = make_float2(rnd_tf32(a.w), rnd_tf32(b.w));
    }
}

// ---------------------------------------------------------------------------
// Dense GEMM core: C = A @ B^T (+ bias). k-dims pre-permuted + rounded.
// CTA 128x128, BK=32, 2-stage cp.async, 2 CTAs/SM. 8 warps (4m x 2n),
// warp tile 32x64, LDS.64 frag loads.
// cmode: 0 dense out; 1 scatter (B,H,T,D) natural d; 2 scatter with perm8 d.
// ---------------------------------------------------------------------------
__device__ __forceinline__
void gemm_core(const float* __restrict__ A, const float* __restrict__ Bm,
               const float* __restrict__ bias, float* __restrict__ Cc,
               int N, int K, int cmode, int round_out, float* sh)
{
    const int KC = K >> 5;
    float* As = sh;                    // [2][128][LDT]
    float* Bs = sh + 2 * 128 * LDT;    // [2][128][LDT]

    const int tid  = threadIdx.x;
    const int warp = tid >> 5;
    const int lane = tid & 31;
    const int g    = lane >> 2;
    const int tig  = lane & 3;
    const int wm   = warp >> 1;        // 0..3  (32-row slice)
    const int wn   = warp & 1;         // 0..1  (64-col slice)

    const int m0 = blockIdx.y * 128;
    const int n0 = blockIdx.x * 128;
    const int lrow = tid >> 1;
    const int lo   = (tid & 1) * 16;

    float acc[2][8][4];
#pragma unroll
    for (int mi = 0; mi < 2; mi++)
#pragma unroll
        for (int ni = 0; ni < 8; ni++)
#pragma unroll
            for (int q = 0; q < 4; q++) acc[mi][ni][q] = 0.f;

    auto load_chunk = [&](int st, int kc) {
        const float* Ag = A + (long long)(m0 + lrow) * K + kc * 32 + lo;
        float* as = As + st * 128 * LDT + lrow * LDT + lo;
#pragma unroll
        for (int i = 0; i < 4; i++) cp_async16(as + i * 4, Ag + i * 4);
        const float* Bg = Bm + (long long)(n0 + lrow) * K + kc * 32 + lo;
        float* bs = Bs + st * 128 * LDT + lrow * LDT + lo;
#pragma unroll
        for (int i = 0; i < 4; i++) cp_async16(bs + i * 4, Bg + i * 4);
        cp_commit();
    };

    auto compute = [&](int st) {
        const uint2* au = (const uint2*)(As + st * 128 * LDT) + (wm * 32) * (LDT / 2);
        const uint2* bu = (const uint2*)(Bs + st * 128 * LDT) + (wn * 64) * (LDT / 2);
#pragma unroll
        for (int ks = 0; ks < 4; ks++) {
            const int kb = ks * 4 + tig;
            uint2 alo[2], ahi[2], bb[8];
#pragma unroll
            for (int mi = 0; mi < 2; mi++) {
                alo[mi] = au[(mi * 16 + g) * (LDT / 2) + kb];
                ahi[mi] = au[(mi * 16 + g + 8) * (LDT / 2) + kb];
            }
#pragma unroll
            for (int ni = 0; ni < 8; ni++)
                bb[ni] = bu[(ni * 8 + g) * (LDT / 2) + kb];
#pragma unroll
            for (int mi = 0; mi < 2; mi++)
#pragma unroll
                for (int ni = 0; ni < 8; ni++)
                    mma_tf32(acc[mi][ni], alo[mi].x, ahi[mi].x, alo[mi].y, ahi[mi].y,
                             bb[ni].x, bb[ni].y);
        }
    };

    load_chunk(0, 0);
    for (int kc = 0; kc < KC; kc++) {
        cp_wait<0>();
        __syncthreads();
        if (kc + 1 < KC) load_chunk((kc + 1) & 1, kc + 1);
        compute(kc & 1);
    }

#pragma unroll
    for (int mi = 0; mi < 2; mi++) {
        const int r0 = m0 + wm * 32 + mi * 16 + g;
        const int r1 = r0 + 8;
#pragma unroll
        for (int ni = 0; ni < 8; ni++) {
            const int c = n0 + wn * 64 + ni * 8 + tig * 2;
            const float b0v = bias ? bias[c]     : 0.f;
            const float b1v = bias ? bias[c + 1] : 0.f;
            float v00 = acc[mi][ni][0] + b0v;
            float v01 = acc[mi][ni][1] + b1v;
            float v10 = acc[mi][ni][2] + b0v;
            float v11 = acc[mi][ni][3] + b1v;
            if (round_out) {
                v00 = rnd_tf32(v00); v01 = rnd_tf32(v01);
                v10 = rnd_tf32(v10); v11 = rnd_tf32(v11);
            }
            if (cmode == 0) {
                *(float2*)&Cc[(long long)r0 * N + c] = make_float2(v00, v01);
                *(float2*)&Cc[(long long)r1 * N + c] = make_float2(v10, v11);
            } else {
                const int h = c >> 6;
                const int dd = c & 63;
                const int b0i = r0 >> 11, t0 = r0 & 2047;
                const int b1i = r1 >> 11, t1 = r1 & 2047;
                float* p0 = &Cc[((long long)(b0i * H_ + h) * T_ + t0) * D_];
                float* p1 = &Cc[((long long)(b1i * H_ + h) * T_ + t1) * D_];
                if (cmode == 2) {
                    const int d0 = (dd & ~7) | perm8(dd & 7);
                    const int d1 = (dd & ~7) | perm8((dd & 7) + 1);
                    p0[d0] = v00; p0[d1] = v01;
                    p1[d0] = v10; p1[d1] = v11;
                } else {
                    *(float2*)&p0[dd] = make_float2(v00, v01);
                    *(float2*)&p1[dd] = make_float2(v10, v11);
                }
            }
        }
    }
}

__global__ __launch_bounds__(256, 2)
void qkv_gemm(const float* __restrict__ xr,
              const float* __restrict__ wq, const float* __restrict__ wk,
              const float* __restrict__ wv,
              const float* __restrict__ bq, const float* __restrict__ bk,
              const float* __restrict__ bv,
              float* __restrict__ q, float* __restrict__ k, float* __restrict__ v)
{
    extern __shared__ float sh[];
    if (blockIdx.z == 0)      gemm_core(xr, wq, bq, q, C_, C_, 2, 1, sh);
    else if (blockIdx.z == 1) gemm_core(xr, wk, bk, k, C_, C_, 2, 1, sh);
    else                      gemm_core(xr, wv, bv, v, C_, C_, 1, 1, sh);
}

__global__ __launch_bounds__(256, 2)
void proj_gemm(const float* __restrict__ A, const float* __restrict__ Bm,
               const float* __restrict__ bias, float* __restrict__ Cc)
{
    extern __shared__ float sh[];
    gemm_core(A, Bm, bias, Cc, C_, C_, 0, 0, sh);
}

// ---------------------------------------------------------------------------
// Two-pass flash attention v3. Per CTA: 128 query rows x one head.
// 8 warps x 16 rows each; warp computes all 64 key-cols per chunk.
// V key-rows stored sigma8-permuted in smem -> sacc feeds P@V mma DIRECTLY
// from registers (no Ps smem, no extra sync).
// smem: Qs[128][LQK], Ks[2][64][LQK], Vs[2][64][LQK], Ms[2][64] = 111,104 B
// -> 2 CTAs/SM.
// ---------------------------------------------------------------------------
__global__ __launch_bounds__(256, 2)
void flash_att(const float* __restrict__ q, const float* __restrict__ k,
               const float* __restrict__ v, const float* __restrict__ mask,
               float* __restrict__ att, float* __restrict__ Y)
{
    const int z = blockIdx.z;
    const int b = z >> 4, h = z & 15;
    const int m0 = blockIdx.y * 128;
    const float* Qg = q + (long long)z * T_ * D_;
    const float* Kg = k + (long long)z * T_ * D_;
    const float* Vg = v + (long long)z * T_ * D_;
    float* Sg = att + (long long)z * T_ * T_;
    const float* mrow = mask + (long long)b * T_;

    extern __shared__ float sh[];
    float* Qs = sh;                          // 128*LQK
    float* Ks = Qs + 128 * LQK;              // 2*64*LQK
    float* Vs = Ks + 2 * 64 * LQK;           // 2*64*LQK
    float* Ms = Vs + 2 * 64 * LQK;           // 2*64

    const int tid  = threadIdx.x;
    const int warp = tid >> 5;               // 0..7: 16-row slice
    const int lane = tid & 31;
    const int g    = lane >> 2;
    const int tig  = lane & 3;

    // Q load (once): 128 rows x 64 (gmem already perm8'd in d)
    {
        const int row = tid >> 1;
        const int off = (tid & 1) * 32;
        const float* src = Qg + (long long)(m0 + row) * D_ + off;
        float* dst = Qs + row * LQK + off;
#pragma unroll
        for (int i = 0; i < 8; i++) cp_async16(dst + i * 4, src + i * 4);
        cp_commit();
    }

    const int krow  = tid >> 2;              // 0..63
    const int kc4   = (tid & 3) * 16;
    const int vprow = (krow & ~7) | sigma8(krow & 7);  // permuted V row

    auto load_k = [&](int st, int kc) {
        const float* src = Kg + (long long)(kc * 64 + krow) * D_ + kc4;
        float* dst = Ks + st * 64 * LQK + krow * LQK + kc4;
#pragma unroll
        for (int i = 0; i < 4; i++) cp_async16(dst + i * 4, src + i * 4);
    };
    auto load_v = [&](int st, int kc) {
        const float* src = Vg + (long long)(kc * 64 + krow) * D_ + kc4;
        float* dst = Vs + st * 64 * LQK + vprow * LQK + kc4;
#pragma unroll
        for (int i = 0; i < 4; i++) cp_async16(dst + i * 4, src + i * 4);
    };
    auto load_m = [&](int st, int kc) {
        if (tid < 16) cp_async16(Ms + st * 64 + tid * 4, mrow + kc * 64 + tid * 4);
    };

    // s-mma: warp computes 16 rows x 64 cols vs Ks[st]; LDS.64 frag loads
    float sacc[8][4];
    auto smma = [&](int st) {
#pragma unroll
        for (int ni = 0; ni < 8; ni++)
#pragma unroll
            for (int qq = 0; qq < 4; qq++) sacc[ni][qq] = 0.f;
        const uint2* au = (const uint2*)Qs + (warp * 16) * (LQK / 2);
        const uint2* bu = (const uint2*)(Ks + st * 64 * LQK);
#pragma unroll
        for (int ks = 0; ks < 8; ks++) {
            const int kb = ks * 4 + tig;
            const uint2 alo = au[g * (LQK / 2) + kb];
            const uint2 ahi = au[(g + 8) * (LQK / 2) + kb];
            uint2 bb[8];
#pragma unroll
            for (int ni = 0; ni < 8; ni++)
                bb[ni] = bu[(ni * 8 + g) * (LQK / 2) + kb];
#pragma unroll
            for (int ni = 0; ni < 8; ni++)
                mma_tf32(sacc[ni], alo.x, ahi.x, alo.y, ahi.y, bb[ni].x, bb[ni].y);
        }
    };

    const int NC = T_ / 64;   // 32 chunks

    // ------------------ Pass A: exp-sum (registers only) ------------------
    float rsum0 = 0.f, rsum1 = 0.f;
    load_k(0, 0); cp_commit();
    for (int kc = 0; kc < NC; kc++) {
        cp_wait<0>();
        __syncthreads();
        if (kc + 1 < NC) { load_k((kc + 1) & 1, kc + 1); cp_commit(); }
        smma(kc & 1);
#pragma unroll
        for (int ni = 0; ni < 8; ni++) {
            rsum0 += __expf(sacc[ni][0] * 0.125f) + __expf(sacc[ni][1] * 0.125f);
            rsum1 += __expf(sacc[ni][2] * 0.125f) + __expf(sacc[ni][3] * 0.125f);
        }
    }
    rsum0 += __shfl_xor_sync(0xffffffffu, rsum0, 1);
    rsum0 += __shfl_xor_sync(0xffffffffu, rsum0, 2);
    rsum1 += __shfl_xor_sync(0xffffffffu, rsum1, 1);
    rsum1 += __shfl_xor_sync(0xffffffffu, rsum1, 2);
    const float il0 = 1.f / rsum0;   // row warp*16 + g
    const float il1 = 1.f / rsum1;   // row warp*16 + g + 8

    // ------------------ Pass B: att write + P@V (register-direct) --------
    float yacc[8][4];
#pragma unroll
    for (int ni = 0; ni < 8; ni++) {
        yacc[ni][0] = 0.f; yacc[ni][1] = 0.f;
        yacc[ni][2] = 0.f; yacc[ni][3] = 0.f;
    }

    const int r0 = m0 + warp * 16 + g;
    const int r1 = r0 + 8;

    load_k(0, 0); load_v(0, 0); load_m(0, 0); cp_commit();
    for (int kc = 0; kc < NC; kc++) {
        cp_wait<0>();
        __syncthreads();
        if (kc + 1 < NC) {
            const int st = (kc + 1) & 1;
            load_k(st, kc + 1); load_v(st, kc + 1); load_m(st, kc + 1);
            cp_commit();
        }
        const int st = kc & 1;
        smma(st);

        // For each 8-key block: normalize+mask, write att, feed mma directly.
        const unsigned* vb = (const unsigned*)(Vs + st * 64 * LQK);
#pragma unroll
        for (int kblk = 0; kblk < 8; kblk++) {
            const int cl = kblk * 8 + tig * 2;
            const float mk0 = Ms[st * 64 + cl];
            const float mk1 = Ms[st * 64 + cl + 1];
            const float p00 = __expf(sacc[kblk][0] * 0.125f) * il0 * mk0;
            const float p01 = __expf(sacc[kblk][1] * 0.125f) * il0 * mk1;
            const float p10 = __expf(sacc[kblk][2] * 0.125f) * il1 * mk0;
            const float p11 = __expf(sacc[kblk][3] * 0.125f) * il1 * mk1;
            const long long gc = (long long)kc * 64 + cl;
            __stcs((float2*)&Sg[(long long)r0 * T_ + gc], make_float2(p00, p01));
            __stcs((float2*)&Sg[(long long)r1 * T_ + gc], make_float2(p10, p11));
            // A-fragment: a0=P[g][slot tig], a1=P[g+8][tig], a2=[g][tig+4], a3=[g+8][tig+4]
            const unsigned a0 = cvt_tf32(p00);
            const unsigned a1 = cvt_tf32(p10);
            const unsigned a2 = cvt_tf32(p01);
            const unsigned a3 = cvt_tf32(p11);
            const unsigned* vrow0 = vb + (kblk * 8 + tig) * LQK;
            const unsigned* vrow1 = vb + (kblk * 8 + tig + 4) * LQK;
#pragma unroll
            for (int nc = 0; nc < 8; nc++) {
                const unsigned b0 = vrow0[nc * 8 + g];
                const unsigned b1 = vrow1[nc * 8 + g];
                mma_tf32(yacc[nc], a0, a1, a2, a3, b0, b1);
            }
        }
    }

    // write Y to (B,T,C) with perm8 on d (feeds the permuted-k proj GEMM)
    {
        const int t0 = r0;
        const int t1 = r1;
#pragma unroll
        for (int nc = 0; nc < 8; nc++) {
            const int dd = nc * 8 + tig * 2;
            const int d0 = (dd & ~7) | perm8(dd & 7);
            const int d1 = (dd & ~7) | perm8((dd & 7) + 1);
            float* p0 = &Y[(long long)(b * T_ + t0) * C_ + h * D_];
            float* p1 = &Y[(long long)(b * T_ + t1) * C_ + h * D_];
            p0[d0] = rnd_tf32(yacc[nc][0]);
            p0[d1] = rnd_tf32(yacc[nc][1]);
            p1[d0] = rnd_tf32(yacc[nc][2]);
            p1[d1] = rnd_tf32(yacc[nc][3]);
        }
    }
}

// ---------------------------------------------------------------------------
// Launch
// ---------------------------------------------------------------------------
extern "C" void kernel_launch(void* const* d_in, const int* in_sizes, int n_in,
                              void* d_out, int out_size)
{
    const float* x    = (const float*)d_in[0];
    const float* mask = (const float*)d_in[2];
    const float* Wq   = (const float*)d_in[3];
    const float* bq   = (const float*)d_in[4];
    const float* Wk   = (const float*)d_in[5];
    const float* bk   = (const float*)d_in[6];
    const float* Wv   = (const float*)d_in[7];
    const float* bv   = (const float*)d_in[8];
    const float* Wp   = (const float*)d_in[9];
    const float* bp   = (const float*)d_in[10];
    float* out = (float*)d_out;

    float *pq, *pk, *pv, *py, *patt_fb, *pxr, *pwq, *pwk, *pwv, *pwp;
    cudaGetSymbolAddress((void**)&pq, g_q);
    cudaGetSymbolAddress((void**)&pk, g_k);
    cudaGetSymbolAddress((void**)&pv, g_v);
    cudaGetSymbolAddress((void**)&py, g_yh);
    cudaGetSymbolAddress((void**)&patt_fb, g_att_fb);
    cudaGetSymbolAddress((void**)&pxr, g_xr);
    cudaGetSymbolAddress((void**)&pwq, g_wqr);
    cudaGetSymbolAddress((void**)&pwk, g_wkr);
    cudaGetSymbolAddress((void**)&pwv, g_wvr);
    cudaGetSymbolAddress((void**)&pwp, g_wpr);

    float* yout;
    float* att;
    if ((long long)out_size >= Y_ELEMS + ATT_ELEMS) {
        yout = out;  att = out + Y_ELEMS;
    } else if ((long long)out_size == ATT_ELEMS) {
        yout = nullptr;  att = out;
    } else {
        yout = out;  att = patt_fb;
    }

    const int GEMM_SMEM  = 2 * 2 * 128 * LDT * 4;                   // 81,920 B
    const int FLASH_SMEM = (128 * LQK + 2 * 64 * LQK + 2 * 64 * LQK + 128) * 4; // 111,104 B
    cudaFuncSetAttribute(qkv_gemm,  cudaFuncAttributeMaxDynamicSharedMemorySize, GEMM_SMEM);
    cudaFuncSetAttribute(proj_gemm, cudaFuncAttributeMaxDynamicSharedMemorySize, GEMM_SMEM);
    cudaFuncSetAttribute(flash_att, cudaFuncAttributeMaxDynamicSharedMemorySize, FLASH_SMEM);

    const dim3 blk(256);

    // 0) pre-round + perm8 the k-dims of x and all weights
    round_perm_k<<<(int)(Y_ELEMS / 8 + 255) / 256, 256>>>(x, pxr, (int)(Y_ELEMS / 8));
    round_perm_k<<<(C_ * C_ / 8 + 255) / 256, 256>>>(Wq, pwq, C_ * C_ / 8);
    round_perm_k<<<(C_ * C_ / 8 + 255) / 256, 256>>>(Wk, pwk, C_ * C_ / 8);
    round_perm_k<<<(C_ * C_ / 8 + 255) / 256, 256>>>(Wv, pwv, C_ * C_ / 8);
    round_perm_k<<<(C_ * C_ / 8 + 255) / 256, 256>>>(Wp, pwp, C_ * C_ / 8);

    // 1) merged Q/K/V projections -> rounded, scattered to (B,H,T,D)
    //    (q,k with perm8'd d for the flash kernel; v natural)
    qkv_gemm<<<dim3(C_ / 128, (B_ * T_) / 128, 3), blk, GEMM_SMEM>>>(
        pxr, pwq, pwk, pwv, bq, bk, bv, pq, pk, pv);

    // 2) fused two-pass flash attention: att (written once) + Y heads
    flash_att<<<dim3(1, T_ / 128, B_ * H_), blk, FLASH_SMEM>>>(
        pq, pk, pv, mask, att, py);

    // 3) output projection (py and Wp both k-permuted; output natural)
    if (yout)
        proj_gemm<<<dim3(C_ / 128, (B_ * T_) / 128, 1), blk, GEMM_SMEM>>>(py, pwp, bp, yout);
}

// round 13
// speedup vs baseline: 1.9688x; 1.8408x over previous
#include <cuda_runtime.h>
#include <cuda_fp16.h>
#include <cstdint>
#include <math.h>

#define B_ 4
#define T_ 2048
#define C_ 1024
#define H_ 16
#define D_ 64

static const long long Y_ELEMS   = (long long)B_ * T_ * C_;        // 8,388,608
static const long long ATT_ELEMS = (long long)B_ * H_ * T_ * T_;   // 268,435,456

// Scratch (device globals; halves live inside reinterpreted float arrays)
__device__ float g_q[(size_t)B_ * H_ * T_ * D_ / 2];   // half[B*H*T*D]
__device__ float g_k[(size_t)B_ * H_ * T_ * D_ / 2];
__device__ float g_vT[(size_t)B_ * H_ * T_ * D_ / 2];  // half[B,H,D,T] token-pair-permuted
__device__ float g_yh[(size_t)B_ * T_ * C_ / 2];       // half[B*T*C] pair-permuted C
__device__ float g_att_fb[(size_t)B_ * H_ * T_ * T_];
__device__ float g_xr[(size_t)B_ * T_ * C_ / 2];       // half, pair-permuted k
__device__ float g_wqr[(size_t)C_ * C_ / 2];
__device__ float g_wkr[(size_t)C_ * C_ / 2];
__device__ float g_wvr[(size_t)C_ * C_ / 2];
__device__ float g_wpr[(size_t)C_ * C_ / 2];

// ---------------------------------------------------------------------------
// PTX helpers
// ---------------------------------------------------------------------------
__device__ __forceinline__ void mma_f16(float c[4],
                                        unsigned a0, unsigned a1, unsigned a2, unsigned a3,
                                        unsigned b0, unsigned b1) {
    asm volatile(
        "mma.sync.aligned.m16n8k16.row.col.f32.f16.f16.f32 "
        "{%0,%1,%2,%3},{%4,%5,%6,%7},{%8,%9},{%0,%1,%2,%3};\n"
        : "+f"(c[0]), "+f"(c[1]), "+f"(c[2]), "+f"(c[3])
        : "r"(a0), "r"(a1), "r"(a2), "r"(a3), "r"(b0), "r"(b1));
}

__device__ __forceinline__ unsigned pack_h2(float lo, float hi) {
    __half2 h = __floats2half2_rn(lo, hi);
    return *(unsigned*)&h;
}

__device__ __forceinline__ void cp_async16(void* smem, const void* gmem) {
    uint32_t s = (uint32_t)__cvta_generic_to_shared(smem);
    asm volatile("cp.async.cg.shared.global [%0], [%1], 16;\n" :: "r"(s), "l"(gmem));
}
__device__ __forceinline__ void cp_commit() {
    asm volatile("cp.async.commit_group;\n");
}
template <int N>
__device__ __forceinline__ void cp_wait() {
    asm volatile("cp.async.wait_group %0;\n" :: "n"(N));
}

// pair-permutation: within each 16-half block, logical half2-pair j sits at
// position perm8(j). Fragment pairs (tig, tig+4) become adjacent -> LDS.64.
__device__ __host__ __forceinline__ int perm8(int j) {
    return ((j & 3) << 1) | ((j >> 2) & 1);
}
// token index -> permuted position (pairs of tokens within 16-token blocks)
__device__ __forceinline__ int tperm(int t) {
    return (t & ~15) | (perm8((t >> 1) & 7) << 1) | (t & 1);
}

#define PH 80   // smem pitch in halves (= 40 half2): frag words 8g+2tig, conflict-free

// ---------------------------------------------------------------------------
// fp32 -> fp16 with pair-perm on the contiguous k dim (16 halves per thread)
// ---------------------------------------------------------------------------
__global__ void round_half_perm(const float* __restrict__ in, __half* __restrict__ out,
                                int n16)
{
    int i = blockIdx.x * 256 + threadIdx.x;
    if (i < n16) {
        const float4* src = (const float4*)(in + (size_t)i * 16);
        float f[16];
        *(float4*)(f + 0)  = src[0];
        *(float4*)(f + 4)  = src[1];
        *(float4*)(f + 8)  = src[2];
        *(float4*)(f + 12) = src[3];
        __half2 blk[8];
#pragma unroll
        for (int j = 0; j < 8; j++)
            blk[perm8(j)] = __floats2half2_rn(f[2 * j], f[2 * j + 1]);
        uint4* o = (uint4*)(out + (size_t)i * 16);
        o[0] = ((uint4*)blk)[0];
        o[1] = ((uint4*)blk)[1];
    }
}

// ---------------------------------------------------------------------------
// Dense GEMM: C = A @ B^T (+ bias); A,B half with pair-permuted k.
// CTA 128x128, BK=64 halves (4 k16-blocks), 2-stage cp.async, 2 CTAs/SM.
// 8 warps (4m x 2n), warp tile 32x64. All frag loads LDS.64.
// cmode: 0 fp32 dense out; 2 half scatter (B,H,T,D) pair-perm d (q,k);
//        3 half scatter transposed (B,H,D,T) token-perm (vT).
// ---------------------------------------------------------------------------
__device__ __forceinline__
void gemm_core(const __half* __restrict__ A, const __half* __restrict__ Bm,
               const float* __restrict__ bias, void* __restrict__ Cc,
               int N, int K, int cmode, __half2* sh)
{
    const int KC = K >> 6;                 // 64-half chunks
    __half2* As = sh;                      // [2][128][PH/2]
    __half2* Bs = sh + 2 * 128 * (PH / 2);

    const int tid  = threadIdx.x;
    const int warp = tid >> 5;
    const int lane = tid & 31;
    const int g    = lane >> 2;
    const int tig  = lane & 3;
    const int wm   = warp >> 1;
    const int wn   = warp & 1;

    const int m0 = blockIdx.y * 128;
    const int n0 = blockIdx.x * 128;
    const int lrow = tid >> 1;
    const int lo   = (tid & 1) * 32;       // halves

    float acc[2][8][4];
#pragma unroll
    for (int mi = 0; mi < 2; mi++)
#pragma unroll
        for (int ni = 0; ni < 8; ni++)
#pragma unroll
            for (int q = 0; q < 4; q++) acc[mi][ni][q] = 0.f;

    auto load_chunk = [&](int st, int kc) {
        const __half* Ag = A + (long long)(m0 + lrow) * K + kc * 64 + lo;
        __half* as = (__half*)(As + st * 128 * (PH / 2)) + lrow * PH + lo;
#pragma unroll
        for (int i = 0; i < 4; i++) cp_async16(as + i * 8, Ag + i * 8);
        const __half* Bg = Bm + (long long)(n0 + lrow) * K + kc * 64 + lo;
        __half* bs = (__half*)(Bs + st * 128 * (PH / 2)) + lrow * PH + lo;
#pragma unroll
        for (int i = 0; i < 4; i++) cp_async16(bs + i * 8, Bg + i * 8);
        cp_commit();
    };

    auto compute = [&](int st) {
        const __half2* au = As + st * 128 * (PH / 2) + (wm * 32) * (PH / 2);
        const __half2* bu = Bs + st * 128 * (PH / 2) + (wn * 64) * (PH / 2);
#pragma unroll
        for (int kb = 0; kb < 4; kb++) {
            const int ko = kb * 8 + 2 * tig;
            uint2 alo[2], ahi[2], bb[8];
#pragma unroll
            for (int mi = 0; mi < 2; mi++) {
                alo[mi] = *(const uint2*)(au + (mi * 16 + g) * (PH / 2) + ko);
                ahi[mi] = *(const uint2*)(au + (mi * 16 + g + 8) * (PH / 2) + ko);
            }
#pragma unroll
            for (int ni = 0; ni < 8; ni++)
                bb[ni] = *(const uint2*)(bu + (ni * 8 + g) * (PH / 2) + ko);
#pragma unroll
            for (int mi = 0; mi < 2; mi++)
#pragma unroll
                for (int ni = 0; ni < 8; ni++)
                    mma_f16(acc[mi][ni], alo[mi].x, ahi[mi].x, alo[mi].y, ahi[mi].y,
                            bb[ni].x, bb[ni].y);
        }
    };

    load_chunk(0, 0);
    for (int kc = 0; kc < KC; kc++) {
        cp_wait<0>();
        __syncthreads();
        if (kc + 1 < KC) load_chunk((kc + 1) & 1, kc + 1);
        compute(kc & 1);
    }

#pragma unroll
    for (int mi = 0; mi < 2; mi++) {
        const int r0 = m0 + wm * 32 + mi * 16 + g;
        const int r1 = r0 + 8;
#pragma unroll
        for (int ni = 0; ni < 8; ni++) {
            const int c = n0 + wn * 64 + ni * 8 + tig * 2;
            const float b0v = bias ? bias[c]     : 0.f;
            const float b1v = bias ? bias[c + 1] : 0.f;
            const float v00 = acc[mi][ni][0] + b0v;
            const float v01 = acc[mi][ni][1] + b1v;
            const float v10 = acc[mi][ni][2] + b0v;
            const float v11 = acc[mi][ni][3] + b1v;
            if (cmode == 0) {
                float* Co = (float*)Cc;
                *(float2*)&Co[(long long)r0 * N + c] = make_float2(v00, v01);
                *(float2*)&Co[(long long)r1 * N + c] = make_float2(v10, v11);
            } else {
                const int h  = c >> 6;
                const int dd = c & 63;
                const int b0i = r0 >> 11, t0 = r0 & 2047;
                const int b1i = r1 >> 11, t1 = r1 & 2047;
                __half* Ch = (__half*)Cc;
                if (cmode == 2) {
                    const int pos = (dd & ~15) | (perm8((dd >> 1) & 7) << 1);
                    __half* p0 = Ch + ((long long)(b0i * H_ + h) * T_ + t0) * D_;
                    __half* p1 = Ch + ((long long)(b1i * H_ + h) * T_ + t1) * D_;
                    *(__half2*)(p0 + pos) = __floats2half2_rn(v00, v01);
                    *(__half2*)(p1 + pos) = __floats2half2_rn(v10, v11);
                } else {   // cmode 3: vT[b,h,d,t'] scalar stores
                    const int tp0 = tperm(t0), tp1 = tperm(t1);
                    __half* base0 = Ch + ((long long)(b0i * H_ + h) * D_ + dd) * T_;
                    __half* base1 = Ch + ((long long)(b1i * H_ + h) * D_ + dd) * T_;
                    base0[tp0]      = __float2half_rn(v00);
                    base0[T_ + tp0] = __float2half_rn(v01);   // dd+1 row
                    base1[tp1]      = __float2half_rn(v10);
                    base1[T_ + tp1] = __float2half_rn(v11);
                }
            }
        }
    }
}

__global__ __launch_bounds__(256, 2)
void qkv_gemm(const __half* __restrict__ xr,
              const __half* __restrict__ wq, const __half* __restrict__ wk,
              const __half* __restrict__ wv,
              const float* __restrict__ bq, const float* __restrict__ bk,
              const float* __restrict__ bv,
              __half* __restrict__ q, __half* __restrict__ k, __half* __restrict__ vT)
{
    extern __shared__ __half2 sh2[];
    if (blockIdx.z == 0)      gemm_core(xr, wq, bq, q,  C_, C_, 2, sh2);
    else if (blockIdx.z == 1) gemm_core(xr, wk, bk, k,  C_, C_, 2, sh2);
    else                      gemm_core(xr, wv, bv, vT, C_, C_, 3, sh2);
}

__global__ __launch_bounds__(256, 2)
void proj_gemm(const __half* __restrict__ A, const __half* __restrict__ Bm,
               const float* __restrict__ bias, float* __restrict__ Cc)
{
    extern __shared__ __half2 sh2[];
    gemm_core(A, Bm, bias, Cc, C_, C_, 0, sh2);
}

// ---------------------------------------------------------------------------
// Two-pass flash attention, fp16 mma. Per CTA: 128 query rows x one head.
// 8 warps x 16 rows. QK^T: warp 16x64, k=64 (4 k16-blocks). P@V register-
// direct from the QK^T C-fragments (A-frag = two adjacent C-tiles packed).
// V comes pre-transposed+token-permuted: B-frags are LDS.64.
// smem: Qs[128][PH], Ks[2][64][PH], Vs[2][64][PH] halves + Ms[2][64] f32
//       = 61,952 B -> 2 CTAs/SM easily.
// ---------------------------------------------------------------------------
__global__ __launch_bounds__(256, 2)
void flash_att(const __half* __restrict__ q, const __half* __restrict__ k,
               const __half* __restrict__ vT, const float* __restrict__ mask,
               float* __restrict__ att, __half* __restrict__ Y)
{
    const int z = blockIdx.z;
    const int b = z >> 4, h = z & 15;
    const int m0 = blockIdx.y * 128;
    const __half* Qg = q  + (long long)z * T_ * D_;
    const __half* Kg = k  + (long long)z * T_ * D_;
    const __half* Vg = vT + (long long)z * T_ * D_;   // [D][T] per (b,h)
    float* Sg = att + (long long)z * T_ * T_;
    const float* mrow = mask + (long long)b * T_;

    extern __shared__ __half2 sh2[];
    __half2* Qs = sh2;                         // 128*(PH/2)
    __half2* Ks = Qs + 128 * (PH / 2);         // 2*64*(PH/2)
    __half2* Vs = Ks + 2 * 64 * (PH / 2);      // 2*64*(PH/2)
    float*   Ms = (float*)(Vs + 2 * 64 * (PH / 2));   // 2*64 f32

    const int tid  = threadIdx.x;
    const int warp = tid >> 5;
    const int lane = tid & 31;
    const int g    = lane >> 2;
    const int tig  = lane & 3;

    // Q load (once): 128 rows x 64 halves
    {
        const int row = tid >> 1;
        const int off = (tid & 1) * 32;
        const __half* src = Qg + (long long)(m0 + row) * D_ + off;
        __half* dst = (__half*)Qs + row * PH + off;
#pragma unroll
        for (int i = 0; i < 4; i++) cp_async16(dst + i * 8, src + i * 8);
        cp_commit();
    }

    const int krow = tid >> 2;                 // 0..63
    const int koff = (tid & 3) * 16;           // halves

    auto load_k = [&](int st, int kc) {
        const __half* src = Kg + (long long)(kc * 64 + krow) * D_ + koff;
        __half* dst = (__half*)(Ks + st * 64 * (PH / 2)) + krow * PH + koff;
        cp_async16(dst, src);
        cp_async16(dst + 8, src + 8);
    };
    auto load_v = [&](int st, int kc) {
        // Vs rows = d, cols = 64 keys (token-permuted in gmem already)
        const __half* src = Vg + (long long)krow * T_ + kc * 64 + koff;
        __half* dst = (__half*)(Vs + st * 64 * (PH / 2)) + krow * PH + koff;
        cp_async16(dst, src);
        cp_async16(dst + 8, src + 8);
    };
    auto load_m = [&](int st, int kc) {
        if (tid < 16) cp_async16(Ms + st * 64 + tid * 4, mrow + kc * 64 + tid * 4);
    };

    // QK^T: warp 16 rows x 64 keys, k = 64 d (4 k16-blocks)
    float sacc[8][4];
    auto smma = [&](int st) {
#pragma unroll
        for (int ni = 0; ni < 8; ni++)
#pragma unroll
            for (int qq = 0; qq < 4; qq++) sacc[ni][qq] = 0.f;
        const __half2* au = Qs + (warp * 16) * (PH / 2);
        const __half2* bu = Ks + st * 64 * (PH / 2);
#pragma unroll
        for (int kb = 0; kb < 4; kb++) {
            const int ko = kb * 8 + 2 * tig;
            const uint2 alo = *(const uint2*)(au + g * (PH / 2) + ko);
            const uint2 ahi = *(const uint2*)(au + (g + 8) * (PH / 2) + ko);
            uint2 bb[8];
#pragma unroll
            for (int ni = 0; ni < 8; ni++)
                bb[ni] = *(const uint2*)(bu + (ni * 8 + g) * (PH / 2) + ko);
#pragma unroll
            for (int ni = 0; ni < 8; ni++)
                mma_f16(sacc[ni], alo.x, ahi.x, alo.y, ahi.y, bb[ni].x, bb[ni].y);
        }
    };

    const int NC = T_ / 64;   // 32 chunks

    // ------------------ Pass A: exp-sum (registers only) ------------------
    float rsum0 = 0.f, rsum1 = 0.f;
    load_k(0, 0); cp_commit();
    for (int kc = 0; kc < NC; kc++) {
        cp_wait<0>();
        __syncthreads();
        if (kc + 1 < NC) { load_k((kc + 1) & 1, kc + 1); cp_commit(); }
        smma(kc & 1);
#pragma unroll
        for (int ni = 0; ni < 8; ni++) {
            rsum0 += __expf(sacc[ni][0] * 0.125f) + __expf(sacc[ni][1] * 0.125f);
            rsum1 += __expf(sacc[ni][2] * 0.125f) + __expf(sacc[ni][3] * 0.125f);
        }
    }
    rsum0 += __shfl_xor_sync(0xffffffffu, rsum0, 1);
    rsum0 += __shfl_xor_sync(0xffffffffu, rsum0, 2);
    rsum1 += __shfl_xor_sync(0xffffffffu, rsum1, 1);
    rsum1 += __shfl_xor_sync(0xffffffffu, rsum1, 2);
    const float il0 = 1.f / rsum0;
    const float il1 = 1.f / rsum1;

    // ------------------ Pass B: att write + register-direct P@V ----------
    float yacc[8][4];
#pragma unroll
    for (int ni = 0; ni < 8; ni++) {
        yacc[ni][0] = 0.f; yacc[ni][1] = 0.f;
        yacc[ni][2] = 0.f; yacc[ni][3] = 0.f;
    }

    const int r0 = m0 + warp * 16 + g;
    const int r1 = r0 + 8;

    load_k(0, 0); load_v(0, 0); load_m(0, 0); cp_commit();
    for (int kc = 0; kc < NC; kc++) {
        cp_wait<0>();
        __syncthreads();
        if (kc + 1 < NC) {
            const int st = (kc + 1) & 1;
            load_k(st, kc + 1); load_v(st, kc + 1); load_m(st, kc + 1);
            cp_commit();
        }
        const int st = kc & 1;
        smma(st);

        const __half2* vb = Vs + st * 64 * (PH / 2);
#pragma unroll
        for (int kb = 0; kb < 4; kb++) {
            // two adjacent 8-key C-tiles = one m16n8k16 A fragment
            const int cl0 = kb * 16 + tig * 2;
            const int cl1 = cl0 + 8;
            const float mk00 = Ms[st * 64 + cl0];
            const float mk01 = Ms[st * 64 + cl0 + 1];
            const float mk10 = Ms[st * 64 + cl1];
            const float mk11 = Ms[st * 64 + cl1 + 1];
            const float p00 = __expf(sacc[2 * kb][0] * 0.125f) * il0 * mk00;
            const float p01 = __expf(sacc[2 * kb][1] * 0.125f) * il0 * mk01;
            const float p10 = __expf(sacc[2 * kb][2] * 0.125f) * il1 * mk00;
            const float p11 = __expf(sacc[2 * kb][3] * 0.125f) * il1 * mk01;
            const float q00 = __expf(sacc[2 * kb + 1][0] * 0.125f) * il0 * mk10;
            const float q01 = __expf(sacc[2 * kb + 1][1] * 0.125f) * il0 * mk11;
            const float q10 = __expf(sacc[2 * kb + 1][2] * 0.125f) * il1 * mk10;
            const float q11 = __expf(sacc[2 * kb + 1][3] * 0.125f) * il1 * mk11;
            const long long gc0 = (long long)kc * 64 + cl0;
            const long long gc1 = (long long)kc * 64 + cl1;
            __stcs((float2*)&Sg[(long long)r0 * T_ + gc0], make_float2(p00, p01));
            __stcs((float2*)&Sg[(long long)r1 * T_ + gc0], make_float2(p10, p11));
            __stcs((float2*)&Sg[(long long)r0 * T_ + gc1], make_float2(q00, q01));
            __stcs((float2*)&Sg[(long long)r1 * T_ + gc1], make_float2(q10, q11));
            const unsigned a0 = pack_h2(p00, p01);
            const unsigned a1 = pack_h2(p10, p11);
            const unsigned a2 = pack_h2(q00, q01);
            const unsigned a3 = pack_h2(q10, q11);
            const int ko = kb * 8 + 2 * tig;
#pragma unroll
            for (int nc = 0; nc < 8; nc++) {
                const uint2 bb = *(const uint2*)(vb + (nc * 8 + g) * (PH / 2) + ko);
                mma_f16(yacc[nc], a0, a1, a2, a3, bb.x, bb.y);
            }
        }
    }

    // write Y (half, pair-permuted within each 16 of C) for the proj GEMM
    {
#pragma unroll
        for (int nc = 0; nc < 8; nc++) {
            const int dd = nc * 8 + tig * 2;
            const int pos = h * D_ + ((dd & ~15) | (perm8((dd >> 1) & 7) << 1));
            __half* p0 = Y + (long long)(b * T_ + r0) * C_;
            __half* p1 = Y + (long long)(b * T_ + r1) * C_;
            *(__half2*)(p0 + pos) = __floats2half2_rn(yacc[nc][0], yacc[nc][1]);
            *(__half2*)(p1 + pos) = __floats2half2_rn(yacc[nc][2], yacc[nc][3]);
        }
    }
}

// ---------------------------------------------------------------------------
// Launch
// ---------------------------------------------------------------------------
extern "C" void kernel_launch(void* const* d_in, const int* in_sizes, int n_in,
                              void* d_out, int out_size)
{
    const float* x    = (const float*)d_in[0];
    const float* mask = (const float*)d_in[2];
    const float* Wq   = (const float*)d_in[3];
    const float* bq   = (const float*)d_in[4];
    const float* Wk   = (const float*)d_in[5];
    const float* bk   = (const float*)d_in[6];
    const float* Wv   = (const float*)d_in[7];
    const float* bv   = (const float*)d_in[8];
    const float* Wp   = (const float*)d_in[9];
    const float* bp   = (const float*)d_in[10];
    float* out = (float*)d_out;

    float *pq, *pk, *pvT, *py, *patt_fb, *pxr, *pwq, *pwk, *pwv, *pwp;
    cudaGetSymbolAddress((void**)&pq, g_q);
    cudaGetSymbolAddress((void**)&pk, g_k);
    cudaGetSymbolAddress((void**)&pvT, g_vT);
    cudaGetSymbolAddress((void**)&py, g_yh);
    cudaGetSymbolAddress((void**)&patt_fb, g_att_fb);
    cudaGetSymbolAddress((void**)&pxr, g_xr);
    cudaGetSymbolAddress((void**)&pwq, g_wqr);
    cudaGetSymbolAddress((void**)&pwk, g_wkr);
    cudaGetSymbolAddress((void**)&pwv, g_wvr);
    cudaGetSymbolAddress((void**)&pwp, g_wpr);

    float* yout;
    float* att;
    if ((long long)out_size >= Y_ELEMS + ATT_ELEMS) {
        yout = out;  att = out + Y_ELEMS;
    } else if ((long long)out_size == ATT_ELEMS) {
        yout = nullptr;  att = out;
    } else {
        yout = out;  att = patt_fb;
    }

    const int GEMM_SMEM  = 2 * 2 * 128 * PH * 2;                    // 81,920 B
    const int FLASH_SMEM = (128 + 2 * 64 + 2 * 64) * PH * 2 + 2 * 64 * 4; // 61,952 B
    cudaFuncSetAttribute(qkv_gemm,  cudaFuncAttributeMaxDynamicSharedMemorySize, GEMM_SMEM);
    cudaFuncSetAttribute(proj_gemm, cudaFuncAttributeMaxDynamicSharedMemorySize, GEMM_SMEM);
    cudaFuncSetAttribute(flash_att, cudaFuncAttributeMaxDynamicSharedMemorySize, FLASH_SMEM);

    const dim3 blk(256);

    // 0) fp32 -> fp16 with pair-perm on k
    round_half_perm<<<(int)(Y_ELEMS / 16 + 255) / 256, 256>>>(x, (__half*)pxr, (int)(Y_ELEMS / 16));
    round_half_perm<<<(C_ * C_ / 16 + 255) / 256, 256>>>(Wq, (__half*)pwq, C_ * C_ / 16);
    round_half_perm<<<(C_ * C_ / 16 + 255) / 256, 256>>>(Wk, (__half*)pwk, C_ * C_ / 16);
    round_half_perm<<<(C_ * C_ / 16 + 255) / 256, 256>>>(Wv, (__half*)pwv, C_ * C_ / 16);
    round_half_perm<<<(C_ * C_ / 16 + 255) / 256, 256>>>(Wp, (__half*)pwp, C_ * C_ / 16);

    // 1) merged Q/K/V projections (q,k pair-perm d; v transposed+token-perm)
    qkv_gemm<<<dim3(C_ / 128, (B_ * T_) / 128, 3), blk, GEMM_SMEM>>>(
        (const __half*)pxr, (const __half*)pwq, (const __half*)pwk, (const __half*)pwv,
        bq, bk, bv, (__half*)pq, (__half*)pk, (__half*)pvT);

    // 2) fused two-pass flash attention: att (fp32, written once) + Y (half)
    flash_att<<<dim3(1, T_ / 128, B_ * H_), blk, FLASH_SMEM>>>(
        (const __half*)pq, (const __half*)pk, (const __half*)pvT, mask, att, (__half*)py);

    // 3) output projection (fp32 out + bias)
    if (yout)
        proj_gemm<<<dim3(C_ / 128, (B_ * T_) / 128, 1), blk, GEMM_SMEM>>>(
            (const __half*)py, (const __half*)pwp, bp, yout);
}

// round 14
// speedup vs baseline: 2.0425x; 1.0374x over previous
#include <cuda_runtime.h>
#include <cuda_fp16.h>
#include <cstdint>
#include <math.h>

#define B_ 4
#define T_ 2048
#define C_ 1024
#define H_ 16
#define D_ 64

static const long long Y_ELEMS   = (long long)B_ * T_ * C_;        // 8,388,608
static const long long ATT_ELEMS = (long long)B_ * H_ * T_ * T_;   // 268,435,456

// exp2 argument scale folded into q: 0.125 * log2(e)
#define QSCALE 0.18033688011112043f

// Scratch (device globals; halves live inside reinterpreted float arrays)
__device__ float g_q[(size_t)B_ * H_ * T_ * D_ / 2];   // half[B*H*T*D], pre-scaled by QSCALE
__device__ float g_k[(size_t)B_ * H_ * T_ * D_ / 2];
__device__ float g_vT[(size_t)B_ * H_ * T_ * D_ / 2];  // half[B,H,D,T] token-pair-permuted
__device__ float g_yh[(size_t)B_ * T_ * C_ / 2];       // half[B*T*C] pair-permuted C
__device__ float g_att_fb[(size_t)B_ * H_ * T_ * T_];
__device__ float g_xr[(size_t)B_ * T_ * C_ / 2];       // half, pair-permuted k
__device__ float g_wqr[(size_t)C_ * C_ / 2];
__device__ float g_wkr[(size_t)C_ * C_ / 2];
__device__ float g_wvr[(size_t)C_ * C_ / 2];
__device__ float g_wpr[(size_t)C_ * C_ / 2];

// ---------------------------------------------------------------------------
// PTX helpers
// ---------------------------------------------------------------------------
__device__ __forceinline__ void mma_f16(float c[4],
                                        unsigned a0, unsigned a1, unsigned a2, unsigned a3,
                                        unsigned b0, unsigned b1) {
    asm volatile(
        "mma.sync.aligned.m16n8k16.row.col.f32.f16.f16.f32 "
        "{%0,%1,%2,%3},{%4,%5,%6,%7},{%8,%9},{%0,%1,%2,%3};\n"
        : "+f"(c[0]), "+f"(c[1]), "+f"(c[2]), "+f"(c[3])
        : "r"(a0), "r"(a1), "r"(a2), "r"(a3), "r"(b0), "r"(b1));
}

__device__ __forceinline__ float ex2f(float x) {
    float r;
    asm("ex2.approx.f32 %0, %1;" : "=f"(r) : "f"(x));
    return r;
}

__device__ __forceinline__ unsigned pack_h2(float lo, float hi) {
    __half2 h = __floats2half2_rn(lo, hi);
    return *(unsigned*)&h;
}

__device__ __forceinline__ void cp_async16(void* smem, const void* gmem) {
    uint32_t s = (uint32_t)__cvta_generic_to_shared(smem);
    asm volatile("cp.async.cg.shared.global [%0], [%1], 16;\n" :: "r"(s), "l"(gmem));
}
__device__ __forceinline__ void cp_commit() {
    asm volatile("cp.async.commit_group;\n");
}
template <int N>
__device__ __forceinline__ void cp_wait() {
    asm volatile("cp.async.wait_group %0;\n" :: "n"(N));
}

// pair-permutation: within each 16-half block, logical half2-pair j sits at
// position perm8(j). Fragment pairs (tig, tig+4) become adjacent -> LDS.64.
__device__ __host__ __forceinline__ int perm8(int j) {
    return ((j & 3) << 1) | ((j >> 2) & 1);
}
// token index -> permuted position (pairs of tokens within 16-token blocks)
__device__ __forceinline__ int tperm(int t) {
    return (t & ~15) | (perm8((t >> 1) & 7) << 1) | (t & 1);
}

#define PH 80   // smem pitch in halves (= 40 half2): frag words 8g+2tig, conflict-free

// ---------------------------------------------------------------------------
// Merged fp32 -> fp16 pair-perm rounding for x, Wq, Wk, Wv, Wp (one launch).
// Block ranges: x [0,2048), Wq [2048,2304), Wk [..2560), Wv [..2816), Wp [..3072)
// ---------------------------------------------------------------------------
__global__ void round_half_perm_all(const float* __restrict__ x,
                                    const float* __restrict__ wq,
                                    const float* __restrict__ wk,
                                    const float* __restrict__ wv,
                                    const float* __restrict__ wp,
                                    __half* __restrict__ xo, __half* __restrict__ wqo,
                                    __half* __restrict__ wko, __half* __restrict__ wvo,
                                    __half* __restrict__ wpo)
{
    const int blk = blockIdx.x;
    const float* in; __half* out; int i;
    if (blk < 2048)      { in = x;  out = xo;  i = blk * 256 + threadIdx.x; }
    else if (blk < 2304) { in = wq; out = wqo; i = (blk - 2048) * 256 + threadIdx.x; }
    else if (blk < 2560) { in = wk; out = wko; i = (blk - 2304) * 256 + threadIdx.x; }
    else if (blk < 2816) { in = wv; out = wvo; i = (blk - 2560) * 256 + threadIdx.x; }
    else                 { in = wp; out = wpo; i = (blk - 2816) * 256 + threadIdx.x; }

    const float4* src = (const float4*)(in + (size_t)i * 16);
    float f[16];
    *(float4*)(f + 0)  = src[0];
    *(float4*)(f + 4)  = src[1];
    *(float4*)(f + 8)  = src[2];
    *(float4*)(f + 12) = src[3];
    __half2 b2[8];
#pragma unroll
    for (int j = 0; j < 8; j++)
        b2[perm8(j)] = __floats2half2_rn(f[2 * j], f[2 * j + 1]);
    uint4* o = (uint4*)(out + (size_t)i * 16);
    o[0] = ((uint4*)b2)[0];
    o[1] = ((uint4*)b2)[1];
}

// ---------------------------------------------------------------------------
// Dense GEMM: C = (A @ B^T + bias) * out_scale; A,B half, pair-permuted k.
// CTA 128x128, BK=64 halves, 2-stage cp.async, 2 CTAs/SM. 8 warps (4m x 2n),
// warp tile 32x64. All frag loads LDS.64.
// cmode: 0 fp32 dense out; 2 half scatter (B,H,T,D) pair-perm d (q,k);
//        3 half scatter transposed (B,H,D,T) token-perm (vT).
// ---------------------------------------------------------------------------
__device__ __forceinline__
void gemm_core(const __half* __restrict__ A, const __half* __restrict__ Bm,
               const float* __restrict__ bias, void* __restrict__ Cc,
               int N, int K, int cmode, float out_scale, __half2* sh)
{
    const int KC = K >> 6;                 // 64-half chunks
    __half2* As = sh;                      // [2][128][PH/2]
    __half2* Bs = sh + 2 * 128 * (PH / 2);

    const int tid  = threadIdx.x;
    const int warp = tid >> 5;
    const int lane = tid & 31;
    const int g    = lane >> 2;
    const int tig  = lane & 3;
    const int wm   = warp >> 1;
    const int wn   = warp & 1;

    const int m0 = blockIdx.y * 128;
    const int n0 = blockIdx.x * 128;
    const int lrow = tid >> 1;
    const int lo   = (tid & 1) * 32;       // halves

    float acc[2][8][4];
#pragma unroll
    for (int mi = 0; mi < 2; mi++)
#pragma unroll
        for (int ni = 0; ni < 8; ni++)
#pragma unroll
            for (int q = 0; q < 4; q++) acc[mi][ni][q] = 0.f;

    auto load_chunk = [&](int st, int kc) {
        const __half* Ag = A + (long long)(m0 + lrow) * K + kc * 64 + lo;
        __half* as = (__half*)(As + st * 128 * (PH / 2)) + lrow * PH + lo;
#pragma unroll
        for (int i = 0; i < 4; i++) cp_async16(as + i * 8, Ag + i * 8);
        const __half* Bg = Bm + (long long)(n0 + lrow) * K + kc * 64 + lo;
        __half* bs = (__half*)(Bs + st * 128 * (PH / 2)) + lrow * PH + lo;
#pragma unroll
        for (int i = 0; i < 4; i++) cp_async16(bs + i * 8, Bg + i * 8);
        cp_commit();
    };

    auto compute = [&](int st) {
        const __half2* au = As + st * 128 * (PH / 2) + (wm * 32) * (PH / 2);
        const __half2* bu = Bs + st * 128 * (PH / 2) + (wn * 64) * (PH / 2);
#pragma unroll
        for (int kb = 0; kb < 4; kb++) {
            const int ko = kb * 8 + 2 * tig;
            uint2 alo[2], ahi[2], bb[8];
#pragma unroll
            for (int mi = 0; mi < 2; mi++) {
                alo[mi] = *(const uint2*)(au + (mi * 16 + g) * (PH / 2) + ko);
                ahi[mi] = *(const uint2*)(au + (mi * 16 + g + 8) * (PH / 2) + ko);
            }
#pragma unroll
            for (int ni = 0; ni < 8; ni++)
                bb[ni] = *(const uint2*)(bu + (ni * 8 + g) * (PH / 2) + ko);
#pragma unroll
            for (int mi = 0; mi < 2; mi++)
#pragma unroll
                for (int ni = 0; ni < 8; ni++)
                    mma_f16(acc[mi][ni], alo[mi].x, ahi[mi].x, alo[mi].y, ahi[mi].y,
                            bb[ni].x, bb[ni].y);
        }
    };

    load_chunk(0, 0);
    for (int kc = 0; kc < KC; kc++) {
        cp_wait<0>();
        __syncthreads();
        if (kc + 1 < KC) load_chunk((kc + 1) & 1, kc + 1);
        compute(kc & 1);
    }

#pragma unroll
    for (int mi = 0; mi < 2; mi++) {
        const int r0 = m0 + wm * 32 + mi * 16 + g;
        const int r1 = r0 + 8;
#pragma unroll
        for (int ni = 0; ni < 8; ni++) {
            const int c = n0 + wn * 64 + ni * 8 + tig * 2;
            const float b0v = bias ? bias[c]     : 0.f;
            const float b1v = bias ? bias[c + 1] : 0.f;
            const float v00 = (acc[mi][ni][0] + b0v) * out_scale;
            const float v01 = (acc[mi][ni][1] + b1v) * out_scale;
            const float v10 = (acc[mi][ni][2] + b0v) * out_scale;
            const float v11 = (acc[mi][ni][3] + b1v) * out_scale;
            if (cmode == 0) {
                float* Co = (float*)Cc;
                *(float2*)&Co[(long long)r0 * N + c] = make_float2(v00, v01);
                *(float2*)&Co[(long long)r1 * N + c] = make_float2(v10, v11);
            } else {
                const int h  = c >> 6;
                const int dd = c & 63;
                const int b0i = r0 >> 11, t0 = r0 & 2047;
                const int b1i = r1 >> 11, t1 = r1 & 2047;
                __half* Ch = (__half*)Cc;
                if (cmode == 2) {
                    const int pos = (dd & ~15) | (perm8((dd >> 1) & 7) << 1);
                    __half* p0 = Ch + ((long long)(b0i * H_ + h) * T_ + t0) * D_;
                    __half* p1 = Ch + ((long long)(b1i * H_ + h) * T_ + t1) * D_;
                    *(__half2*)(p0 + pos) = __floats2half2_rn(v00, v01);
                    *(__half2*)(p1 + pos) = __floats2half2_rn(v10, v11);
                } else {   // cmode 3: vT[b,h,d,t'] scalar stores
                    const int tp0 = tperm(t0), tp1 = tperm(t1);
                    __half* base0 = Ch + ((long long)(b0i * H_ + h) * D_ + dd) * T_;
                    __half* base1 = Ch + ((long long)(b1i * H_ + h) * D_ + dd) * T_;
                    base0[tp0]      = __float2half_rn(v00);
                    base0[T_ + tp0] = __float2half_rn(v01);   // dd+1 row
                    base1[tp1]      = __float2half_rn(v10);
                    base1[T_ + tp1] = __float2half_rn(v11);
                }
            }
        }
    }
}

__global__ __launch_bounds__(256, 2)
void qkv_gemm(const __half* __restrict__ xr,
              const __half* __restrict__ wq, const __half* __restrict__ wk,
              const __half* __restrict__ wv,
              const float* __restrict__ bq, const float* __restrict__ bk,
              const float* __restrict__ bv,
              __half* __restrict__ q, __half* __restrict__ k, __half* __restrict__ vT)
{
    extern __shared__ __half2 sh2[];
    if (blockIdx.z == 0)      gemm_core(xr, wq, bq, q,  C_, C_, 2, QSCALE, sh2);
    else if (blockIdx.z == 1) gemm_core(xr, wk, bk, k,  C_, C_, 2, 1.f, sh2);
    else                      gemm_core(xr, wv, bv, vT, C_, C_, 3, 1.f, sh2);
}

__global__ __launch_bounds__(256, 2)
void proj_gemm(const __half* __restrict__ A, const __half* __restrict__ Bm,
               const float* __restrict__ bias, float* __restrict__ Cc)
{
    extern __shared__ __half2 sh2[];
    gemm_core(A, Bm, bias, Cc, C_, C_, 0, 1.f, sh2);
}

// ---------------------------------------------------------------------------
// Two-pass flash attention, fp16 mma. Per CTA: 128 query rows x one head.
// Q is pre-scaled by 0.125*log2e -> softmax weight = ex2(s) directly.
// 8 warps x 16 rows. P@V register-direct from the QK^T C-fragments.
// smem: Qs[128][PH], Ks[2][64][PH], Vs[2][64][PH] halves + Ms[2][64] f32
//       = 61,952 B -> 2 CTAs/SM.
// ---------------------------------------------------------------------------
__global__ __launch_bounds__(256, 2)
void flash_att(const __half* __restrict__ q, const __half* __restrict__ k,
               const __half* __restrict__ vT, const float* __restrict__ mask,
               float* __restrict__ att, __half* __restrict__ Y)
{
    const int z = blockIdx.z;
    const int b = z >> 4, h = z & 15;
    const int m0 = blockIdx.y * 128;
    const __half* Qg = q  + (long long)z * T_ * D_;
    const __half* Kg = k  + (long long)z * T_ * D_;
    const __half* Vg = vT + (long long)z * T_ * D_;   // [D][T] per (b,h)
    float* Sg = att + (long long)z * T_ * T_;
    const float* mrow = mask + (long long)b * T_;

    extern __shared__ __half2 sh2[];
    __half2* Qs = sh2;                         // 128*(PH/2)
    __half2* Ks = Qs + 128 * (PH / 2);         // 2*64*(PH/2)
    __half2* Vs = Ks + 2 * 64 * (PH / 2);      // 2*64*(PH/2)
    float*   Ms = (float*)(Vs + 2 * 64 * (PH / 2));   // 2*64 f32

    const int tid  = threadIdx.x;
    const int warp = tid >> 5;
    const int lane = tid & 31;
    const int g    = lane >> 2;
    const int tig  = lane & 3;

    // Q load (once): 128 rows x 64 halves
    {
        const int row = tid >> 1;
        const int off = (tid & 1) * 32;
        const __half* src = Qg + (long long)(m0 + row) * D_ + off;
        __half* dst = (__half*)Qs + row * PH + off;
#pragma unroll
        for (int i = 0; i < 4; i++) cp_async16(dst + i * 8, src + i * 8);
        cp_commit();
    }

    const int krow = tid >> 2;                 // 0..63
    const int koff = (tid & 3) * 16;           // halves

    auto load_k = [&](int st, int kc) {
        const __half* src = Kg + (long long)(kc * 64 + krow) * D_ + koff;
        __half* dst = (__half*)(Ks + st * 64 * (PH / 2)) + krow * PH + koff;
        cp_async16(dst, src);
        cp_async16(dst + 8, src + 8);
    };
    auto load_v = [&](int st, int kc) {
        const __half* src = Vg + (long long)krow * T_ + kc * 64 + koff;
        __half* dst = (__half*)(Vs + st * 64 * (PH / 2)) + krow * PH + koff;
        cp_async16(dst, src);
        cp_async16(dst + 8, src + 8);
    };
    auto load_m = [&](int st, int kc) {
        if (tid < 16) cp_async16(Ms + st * 64 + tid * 4, mrow + kc * 64 + tid * 4);
    };

    // QK^T: warp 16 rows x 64 keys, k = 64 d (4 k16-blocks)
    float sacc[8][4];
    auto smma = [&](int st) {
#pragma unroll
        for (int ni = 0; ni < 8; ni++)
#pragma unroll
            for (int qq = 0; qq < 4; qq++) sacc[ni][qq] = 0.f;
        const __half2* au = Qs + (warp * 16) * (PH / 2);
        const __half2* bu = Ks + st * 64 * (PH / 2);
#pragma unroll
        for (int kb = 0; kb < 4; kb++) {
            const int ko = kb * 8 + 2 * tig;
            const uint2 alo = *(const uint2*)(au + g * (PH / 2) + ko);
            const uint2 ahi = *(const uint2*)(au + (g + 8) * (PH / 2) + ko);
            uint2 bb[8];
#pragma unroll
            for (int ni = 0; ni < 8; ni++)
                bb[ni] = *(const uint2*)(bu + (ni * 8 + g) * (PH / 2) + ko);
#pragma unroll
            for (int ni = 0; ni < 8; ni++)
                mma_f16(sacc[ni], alo.x, ahi.x, alo.y, ahi.y, bb[ni].x, bb[ni].y);
        }
    };

    const int NC = T_ / 64;   // 32 chunks

    // ------------------ Pass A: exp2-sum (registers only) -----------------
    float rsum0 = 0.f, rsum1 = 0.f;
    load_k(0, 0); cp_commit();
    for (int kc = 0; kc < NC; kc++) {
        cp_wait<0>();
        __syncthreads();
        if (kc + 1 < NC) { load_k((kc + 1) & 1, kc + 1); cp_commit(); }
        smma(kc & 1);
#pragma unroll
        for (int ni = 0; ni < 8; ni++) {
            rsum0 += ex2f(sacc[ni][0]) + ex2f(sacc[ni][1]);
            rsum1 += ex2f(sacc[ni][2]) + ex2f(sacc[ni][3]);
        }
    }
    rsum0 += __shfl_xor_sync(0xffffffffu, rsum0, 1);
    rsum0 += __shfl_xor_sync(0xffffffffu, rsum0, 2);
    rsum1 += __shfl_xor_sync(0xffffffffu, rsum1, 1);
    rsum1 += __shfl_xor_sync(0xffffffffu, rsum1, 2);
    const float il0 = 1.f / rsum0;
    const float il1 = 1.f / rsum1;

    // ------------------ Pass B: att write + register-direct P@V ----------
    float yacc[8][4];
#pragma unroll
    for (int ni = 0; ni < 8; ni++) {
        yacc[ni][0] = 0.f; yacc[ni][1] = 0.f;
        yacc[ni][2] = 0.f; yacc[ni][3] = 0.f;
    }

    const int r0 = m0 + warp * 16 + g;
    const int r1 = r0 + 8;

    load_k(0, 0); load_v(0, 0); load_m(0, 0); cp_commit();
    for (int kc = 0; kc < NC; kc++) {
        cp_wait<0>();
        __syncthreads();
        if (kc + 1 < NC) {
            const int st = (kc + 1) & 1;
            load_k(st, kc + 1); load_v(st, kc + 1); load_m(st, kc + 1);
            cp_commit();
        }
        const int st = kc & 1;
        smma(st);

        const __half2* vb = Vs + st * 64 * (PH / 2);
#pragma unroll
        for (int kb = 0; kb < 4; kb++) {
            // two adjacent 8-key C-tiles = one m16n8k16 A fragment
            const int cl0 = kb * 16 + tig * 2;
            const int cl1 = cl0 + 8;
            const float mk00 = Ms[st * 64 + cl0];
            const float mk01 = Ms[st * 64 + cl0 + 1];
            const float mk10 = Ms[st * 64 + cl1];
            const float mk11 = Ms[st * 64 + cl1 + 1];
            const float p00 = ex2f(sacc[2 * kb][0]) * il0 * mk00;
            const float p01 = ex2f(sacc[2 * kb][1]) * il0 * mk01;
            const float p10 = ex2f(sacc[2 * kb][2]) * il1 * mk00;
            const float p11 = ex2f(sacc[2 * kb][3]) * il1 * mk01;
            const float q00 = ex2f(sacc[2 * kb + 1][0]) * il0 * mk10;
            const float q01 = ex2f(sacc[2 * kb + 1][1]) * il0 * mk11;
            const float q10 = ex2f(sacc[2 * kb + 1][2]) * il1 * mk10;
            const float q11 = ex2f(sacc[2 * kb + 1][3]) * il1 * mk11;
            const long long gc0 = (long long)kc * 64 + cl0;
            const long long gc1 = (long long)kc * 64 + cl1;
            __stcs((float2*)&Sg[(long long)r0 * T_ + gc0], make_float2(p00, p01));
            __stcs((float2*)&Sg[(long long)r1 * T_ + gc0], make_float2(p10, p11));
            __stcs((float2*)&Sg[(long long)r0 * T_ + gc1], make_float2(q00, q01));
            __stcs((float2*)&Sg[(long long)r1 * T_ + gc1], make_float2(q10, q11));
            const unsigned a0 = pack_h2(p00, p01);
            const unsigned a1 = pack_h2(p10, p11);
            const unsigned a2 = pack_h2(q00, q01);
            const unsigned a3 = pack_h2(q10, q11);
            const int ko = kb * 8 + 2 * tig;
#pragma unroll
            for (int nc = 0; nc < 8; nc++) {
                const uint2 bb = *(const uint2*)(vb + (nc * 8 + g) * (PH / 2) + ko);
                mma_f16(yacc[nc], a0, a1, a2, a3, bb.x, bb.y);
            }
        }
    }

    // write Y (half, pair-permuted within each 16 of C) for the proj GEMM
    {
#pragma unroll
        for (int nc = 0; nc < 8; nc++) {
            const int dd = nc * 8 + tig * 2;
            const int pos = h * D_ + ((dd & ~15) | (perm8((dd >> 1) & 7) << 1));
            __half* p0 = Y + (long long)(b * T_ + r0) * C_;
            __half* p1 = Y + (long long)(b * T_ + r1) * C_;
            *(__half2*)(p0 + pos) = __floats2half2_rn(yacc[nc][0], yacc[nc][1]);
            *(__half2*)(p1 + pos) = __floats2half2_rn(yacc[nc][2], yacc[nc][3]);
        }
    }
}

// ---------------------------------------------------------------------------
// Launch
// ---------------------------------------------------------------------------
extern "C" void kernel_launch(void* const* d_in, const int* in_sizes, int n_in,
                              void* d_out, int out_size)
{
    const float* x    = (const float*)d_in[0];
    const float* mask = (const float*)d_in[2];
    const float* Wq   = (const float*)d_in[3];
    const float* bq   = (const float*)d_in[4];
    const float* Wk   = (const float*)d_in[5];
    const float* bk   = (const float*)d_in[6];
    const float* Wv   = (const float*)d_in[7];
    const float* bv   = (const float*)d_in[8];
    const float* Wp   = (const float*)d_in[9];
    const float* bp   = (const float*)d_in[10];
    float* out = (float*)d_out;

    float *pq, *pk, *pvT, *py, *patt_fb, *pxr, *pwq, *pwk, *pwv, *pwp;
    cudaGetSymbolAddress((void**)&pq, g_q);
    cudaGetSymbolAddress((void**)&pk, g_k);
    cudaGetSymbolAddress((void**)&pvT, g_vT);
    cudaGetSymbolAddress((void**)&py, g_yh);
    cudaGetSymbolAddress((void**)&patt_fb, g_att_fb);
    cudaGetSymbolAddress((void**)&pxr, g_xr);
    cudaGetSymbolAddress((void**)&pwq, g_wqr);
    cudaGetSymbolAddress((void**)&pwk, g_wkr);
    cudaGetSymbolAddress((void**)&pwv, g_wvr);
    cudaGetSymbolAddress((void**)&pwp, g_wpr);

    float* yout;
    float* att;
    if ((long long)out_size >= Y_ELEMS + ATT_ELEMS) {
        yout = out;  att = out + Y_ELEMS;
    } else if ((long long)out_size == ATT_ELEMS) {
        yout = nullptr;  att = out;
    } else {
        yout = out;  att = patt_fb;
    }

    const int GEMM_SMEM  = 2 * 2 * 128 * PH * 2;                    // 81,920 B
    const int FLASH_SMEM = (128 + 2 * 64 + 2 * 64) * PH * 2 + 2 * 64 * 4; // 61,952 B
    cudaFuncSetAttribute(qkv_gemm,  cudaFuncAttributeMaxDynamicSharedMemorySize, GEMM_SMEM);
    cudaFuncSetAttribute(proj_gemm, cudaFuncAttributeMaxDynamicSharedMemorySize, GEMM_SMEM);
    cudaFuncSetAttribute(flash_att, cudaFuncAttributeMaxDynamicSharedMemorySize, FLASH_SMEM);

    const dim3 blk(256);

    // 0) one merged fp32 -> fp16 pair-perm rounding launch (x + 4 weights)
    round_half_perm_all<<<3072, 256>>>(x, Wq, Wk, Wv, Wp,
                                       (__half*)pxr, (__half*)pwq, (__half*)pwk,
                                       (__half*)pwv, (__half*)pwp);

    // 1) merged Q/K/V projections (q scaled by QSCALE; v transposed+token-perm)
    qkv_gemm<<<dim3(C_ / 128, (B_ * T_) / 128, 3), blk, GEMM_SMEM>>>(
        (const __half*)pxr, (const __half*)pwq, (const __half*)pwk, (const __half*)pwv,
        bq, bk, bv, (__half*)pq, (__half*)pk, (__half*)pvT);

    // 2) fused two-pass flash attention: att (fp32, written once) + Y (half)
    flash_att<<<dim3(1, T_ / 128, B_ * H_), blk, FLASH_SMEM>>>(
        (const __half*)pq, (const __half*)pk, (const __half*)pvT, mask, att, (__half*)py);

    // 3) output projection (fp32 out + bias)
    if (yout)
        proj_gemm<<<dim3(C_ / 128, (B_ * T_) / 128, 1), blk, GEMM_SMEM>>>(
            (const __half*)py, (const __half*)pwp, bp, yout);
}